// round 10
// baseline (speedup 1.0000x reference)
#include <cuda_runtime.h>
#include <stdint.h>
#include <math.h>

#define NI 700
#define NIP 704
#define H 4096
#define T 1000
#define TPAD 1024
#define O 20

// ---------------- scratch (static device memory; no allocs) ----------------
__device__ __align__(16) int8_t  g_w1p[H * NIP];        // w1 packed int8, padded 700->704
__device__ __align__(16) int8_t  g_sp [TPAD * NIP];     // spikes packed int8, padded rows+cols
__device__ __align__(16) uint8_t g_v1B[(size_t)H * H];  // v1B[k][h] = v1[h][k] + 8  (0..15)
__device__ __align__(16) int8_t  g_w2T[H * 32];         // w2T[k][o], padded 20->32
__device__ __align__(16) int     g_in [T * H];          // in_all[t][h], int32 (exact)
__device__ int g_mode;  // input dtype: 0=int64, 1=int32, 2=float32, 3=float64

// ---------------- input dtype probe (on w1: dense values in [-8,7]) ----------------
__global__ void detect_dtype_kernel(const void* __restrict__ p) {
    const int* w = (const int*)p;
    bool i64 = true;
    for (int i = 0; i < 8; i++) {
        int lo = w[2 * i], hi = w[2 * i + 1];
        if (!(lo >= -8 && lo <= 7 && hi == (lo < 0 ? -1 : 0))) i64 = false;
    }
    if (i64) { g_mode = 0; return; }
    bool i32 = true;
    for (int i = 0; i < 16; i++) {
        int v = w[i];
        if (!(v >= -8 && v <= 7)) i32 = false;
    }
    if (i32) { g_mode = 1; return; }
    bool f32 = true;
    for (int i = 0; i < 16; i++) {
        float f = __int_as_float(w[i]);
        if (!(isfinite(f) && fabsf(f) <= 8.0f && f == truncf(f))) f32 = false;
    }
    if (f32) { g_mode = 2; return; }
    g_mode = 3;  // float64
}

__device__ __forceinline__ int load_elem(const void* p, long idx) {
    switch (g_mode) {
        case 0:  return (int)((const long long*)p)[idx];
        case 1:  return ((const int*)p)[idx];
        case 2:  return (int)((const float*)p)[idx];
        default: return (int)((const double*)p)[idx];
    }
}

// ---------------- pack kernels ----------------
__global__ void pack_w1_kernel(const void* __restrict__ w1) {
    int idx = blockIdx.x * blockDim.x + threadIdx.x;
    if (idx >= H * NIP) return;
    int h = idx / NIP, c = idx - h * NIP;
    g_w1p[idx] = (c < NI) ? (int8_t)load_elem(w1, (long)h * NI + c) : (int8_t)0;
}

__global__ void pack_sp_kernel(const void* __restrict__ spk) {
    int idx = blockIdx.x * blockDim.x + threadIdx.x;
    if (idx >= TPAD * NIP) return;
    int t = idx / NIP, c = idx - t * NIP;
    g_sp[idx] = (t < T && c < NI) ? (int8_t)load_elem(spk, (long)t * NI + c) : (int8_t)0;
}

__global__ void pack_w2_kernel(const void* __restrict__ w2) {
    int idx = blockIdx.x * blockDim.x + threadIdx.x;
    if (idx >= H * 32) return;
    int k = idx >> 5, o = idx & 31;
    g_w2T[idx] = (o < O) ? (int8_t)load_elem(w2, (long)o * H + k) : (int8_t)0;
}

// tiled transpose: v1[h][k] -> g_v1B[k][h] = v1[h][k] + 8 (biased uint8)
__global__ void pack_v1T_kernel(const void* __restrict__ v1) {
    __shared__ uint8_t tile[64][65];
    int kb = blockIdx.x * 64;
    int hb = blockIdx.y * 64;
    for (int i = threadIdx.x; i < 64 * 64; i += 256) {
        int r = i >> 6, c = i & 63;          // r = h-local, c = k-local
        tile[c][r] = (uint8_t)(load_elem(v1, (long)(hb + r) * H + (kb + c)) + 8);
    }
    __syncthreads();
    for (int i = threadIdx.x; i < 64 * 64; i += 256) {
        int r = i >> 6, c = i & 63;          // r = k-local, c = h-local
        g_v1B[(size_t)(kb + r) * H + (hb + c)] = tile[r][c];
    }
}

// ---------------- feed-forward GEMM via IMMA tensor cores ----------------
__device__ __forceinline__ void mma16832(int* d, const unsigned* a, const unsigned* b) {
    asm volatile(
        "mma.sync.aligned.m16n8k32.row.col.s32.s8.s8.s32 "
        "{%0,%1,%2,%3},{%4,%5,%6,%7},{%8,%9},{%0,%1,%2,%3};"
        : "+r"(d[0]), "+r"(d[1]), "+r"(d[2]), "+r"(d[3])
        : "r"(a[0]), "r"(a[1]), "r"(a[2]), "r"(a[3]), "r"(b[0]), "r"(b[1]));
}

__global__ void __launch_bounds__(256, 1) gemm_in_imma() {
    const int warp = threadIdx.x >> 5;
    const int lane = threadIdx.x & 31;
    const int gid = lane >> 2;           // group id (0..7)
    const int tig = lane & 3;            // thread-in-group (0..3)
    const int tb = blockIdx.x * 32;      // t-tile base (rows, padded to 1024)
    const int hb = blockIdx.y * 256 + warp * 32;  // h-tile base

    int acc[2][4][4];
#pragma unroll
    for (int mt = 0; mt < 2; mt++)
#pragma unroll
        for (int nt = 0; nt < 4; nt++)
#pragma unroll
            for (int r = 0; r < 4; r++) acc[mt][nt][r] = 0;

    const int8_t* As = g_sp  + (size_t)(tb + gid) * NIP + tig * 4;
    const int8_t* Bs = g_w1p + (size_t)(hb + gid) * NIP + tig * 4;

    for (int kk = 0; kk < NIP; kk += 32) {
        unsigned a[2][4], b[4][2];
#pragma unroll
        for (int mt = 0; mt < 2; mt++) {
            const int8_t* ap = As + (size_t)mt * 16 * NIP + kk;
            a[mt][0] = *(const unsigned*)(ap);
            a[mt][1] = *(const unsigned*)(ap + 8 * NIP);
            a[mt][2] = *(const unsigned*)(ap + 16);
            a[mt][3] = *(const unsigned*)(ap + 8 * NIP + 16);
        }
#pragma unroll
        for (int nt = 0; nt < 4; nt++) {
            const int8_t* bp = Bs + (size_t)nt * 8 * NIP + kk;
            b[nt][0] = *(const unsigned*)(bp);
            b[nt][1] = *(const unsigned*)(bp + 16);
        }
#pragma unroll
        for (int mt = 0; mt < 2; mt++)
#pragma unroll
            for (int nt = 0; nt < 4; nt++)
                mma16832(acc[mt][nt], a[mt], b[nt]);
    }

#pragma unroll
    for (int mt = 0; mt < 2; mt++) {
#pragma unroll
        for (int nt = 0; nt < 4; nt++) {
            int row0 = tb + mt * 16 + gid;
            int col = hb + nt * 8 + tig * 2;
            if (row0 < T)
                *(int2*)(g_in + (size_t)row0 * H + col) =
                    make_int2(acc[mt][nt][0], acc[mt][nt][1]);
            int row1 = row0 + 8;
            if (row1 < T)
                *(int2*)(g_in + (size_t)row1 * H + col) =
                    make_int2(acc[mt][nt][2], acc[mt][nt][3]);
        }
    }
}

// LIF update for one neuron (constant index i at expansion site).
#define LIF1(i, icval) do {                                                    \
    int m = ((spm >> (i)) & 1u) ? 0 : mem[i];                                  \
    nm |= (unsigned)(m > 1) << (i);                                            \
    mem[i] = m - (m >> 3) + syn[i];                                            \
    syn[i] = syn[i] - (syn[i] >> 4) + (icval) + (int)accu[i] - bias;           \
} while (0)

// ---------------- sequential recurrence: one persistent CTA, 288 threads ----
// Threads 0..255: gather+LIF, 16 neurons each. Biased-byte accumulation with
// EXPLICIT 4-deep load batching (MLP) inside each <=16-row chunk. Warp 8:
// readout, also 4-deep batched. One barrier per step.
__global__ void __launch_bounds__(288, 1) snn_recur_kernel(void* __restrict__ out) {
    __shared__ int listbuf[2][H];
    __shared__ int cnts[T + 1];
    const int tid = threadIdx.x;
    const bool gth = tid < 256;
    const int h0 = tid << 4;             // first neuron (also row byte offset)
    const int ro_lane = tid - 256;

    int mem[16], syn[16];
    unsigned accu[16];
    unsigned spm = 0;                    // previous-step spike bitmask
    int rm = 0, rs = 0;                  // readout state
#pragma unroll
    for (int i = 0; i < 16; i++) { mem[i] = 0; syn[i] = 0; }

    for (int i = tid; i <= T; i += 288) cnts[i] = 0;
    __syncthreads();

    for (int t = 0; t < T; t++) {
        const int p = t & 1, pn = p ^ 1;
        const int n = cnts[t];           // spikes produced at step t-1
        const int* lb = listbuf[p];

        if (gth) {
            // prefetch this step's input currents (hidden behind the gather)
            const int4* gi = (const int4*)(g_in + (size_t)t * H + h0);
            int4 ic0 = __ldg(gi + 0), ic1 = __ldg(gi + 1);
            int4 ic2 = __ldg(gi + 2), ic3 = __ldg(gi + 3);

#pragma unroll
            for (int i = 0; i < 16; i++) accu[i] = 0;

            const uint8_t* vbase = g_v1B + h0;
            int j = 0;
            while (j < n) {
                int e = j + 16; if (e > n) e = n;     // chunk of <=16 rows
                unsigned pa = 0, pb = 0, pc = 0, pd = 0;
                // 4-deep batches: independent LDG.128s, then sum
                for (; j + 4 <= e; j += 4) {
                    uint4 A = *(const uint4*)(vbase + ((size_t)lb[j]     << 12));
                    uint4 B = *(const uint4*)(vbase + ((size_t)lb[j + 1] << 12));
                    uint4 C = *(const uint4*)(vbase + ((size_t)lb[j + 2] << 12));
                    uint4 D = *(const uint4*)(vbase + ((size_t)lb[j + 3] << 12));
                    pa += A.x + B.x + C.x + D.x;
                    pb += A.y + B.y + C.y + D.y;
                    pc += A.z + B.z + C.z + D.z;
                    pd += A.w + B.w + C.w + D.w;
                }
                for (; j < e; j++) {      // tail (0..3 rows)
                    uint4 R = *(const uint4*)(vbase + ((size_t)lb[j] << 12));
                    pa += R.x; pb += R.y; pc += R.z; pd += R.w;
                }
                accu[0]  = __dp4a(pa, 0x00000001u, accu[0]);
                accu[1]  = __dp4a(pa, 0x00000100u, accu[1]);
                accu[2]  = __dp4a(pa, 0x00010000u, accu[2]);
                accu[3]  = __dp4a(pa, 0x01000000u, accu[3]);
                accu[4]  = __dp4a(pb, 0x00000001u, accu[4]);
                accu[5]  = __dp4a(pb, 0x00000100u, accu[5]);
                accu[6]  = __dp4a(pb, 0x00010000u, accu[6]);
                accu[7]  = __dp4a(pb, 0x01000000u, accu[7]);
                accu[8]  = __dp4a(pc, 0x00000001u, accu[8]);
                accu[9]  = __dp4a(pc, 0x00000100u, accu[9]);
                accu[10] = __dp4a(pc, 0x00010000u, accu[10]);
                accu[11] = __dp4a(pc, 0x01000000u, accu[11]);
                accu[12] = __dp4a(pd, 0x00000001u, accu[12]);
                accu[13] = __dp4a(pd, 0x00000100u, accu[13]);
                accu[14] = __dp4a(pd, 0x00010000u, accu[14]);
                accu[15] = __dp4a(pd, 0x01000000u, accu[15]);
            }
            const int bias = n * 8;

            // ---- LIF (reset by prev spike -> threshold -> decay/integrate) ----
            unsigned nm = 0;
            LIF1(0,  ic0.x); LIF1(1,  ic0.y); LIF1(2,  ic0.z); LIF1(3,  ic0.w);
            LIF1(4,  ic1.x); LIF1(5,  ic1.y); LIF1(6,  ic1.z); LIF1(7,  ic1.w);
            LIF1(8,  ic2.x); LIF1(9,  ic2.y); LIF1(10, ic2.z); LIF1(11, ic2.w);
            LIF1(12, ic3.x); LIF1(13, ic3.y); LIF1(14, ic3.z); LIF1(15, ic3.w);

            // ---- append new spikes ----
            int c = __popc(nm);
            if (c) {
                int pos = atomicAdd(&cnts[t + 1], c);
                unsigned b = nm;
                while (b) {
                    int i = __ffs(b) - 1;
                    b &= b - 1;
                    listbuf[pn][pos++] = h0 + i;
                }
            }
            spm = nm;
        } else if (t > 0) {
            // ---- readout for step t-1 (warp 8, 4-deep batched loads) ----
            int ro = 0;
            int j = 0;
            for (; j + 4 <= n; j += 4) {
                int a = (int)g_w2T[(lb[j]     << 5) + ro_lane];
                int b = (int)g_w2T[(lb[j + 1] << 5) + ro_lane];
                int c = (int)g_w2T[(lb[j + 2] << 5) + ro_lane];
                int d = (int)g_w2T[(lb[j + 3] << 5) + ro_lane];
                ro += a + b + c + d;
            }
            for (; j < n; j++)
                ro += (int)g_w2T[(lb[j] << 5) + ro_lane];
            rm = rm - (rm >> 3) + rs;
            rs = rs - (rs >> 4) + ro;
            if (ro_lane < O) ((float*)out)[ro_lane * T + (t - 1)] = (float)rm;
        }

        __syncthreads();                 // publish listbuf[pn] + cnts[t+1]
    }

    // ---- epilogue: readout for t = T-1 (no gather needed) ----
    if (!gth) {
        rm = rm - (rm >> 3) + rs;
        if (ro_lane < O) ((float*)out)[ro_lane * T + (T - 1)] = (float)rm;
    }
}

// ---------------- launcher ----------------
extern "C" void kernel_launch(void* const* d_in, const int* in_sizes, int n_in,
                              void* d_out, int out_size) {
    // Identify inputs by element count (order-independent; all sizes unique).
    const void *spk = 0, *w1 = 0, *v1 = 0, *w2 = 0;
    for (int i = 0; i < n_in; i++) {
        switch (in_sizes[i]) {
            case T * NI:  spk = d_in[i]; break;   // 700,000
            case H * NI:  w1  = d_in[i]; break;   // 2,867,200
            case H * H:   v1  = d_in[i]; break;   // 16,777,216
            case O * H:   w2  = d_in[i]; break;   // 81,920
        }
    }

    detect_dtype_kernel<<<1, 1>>>(w1);

    pack_w1_kernel<<<(H * NIP + 255) / 256, 256>>>(w1);
    pack_sp_kernel<<<(TPAD * NIP + 255) / 256, 256>>>(spk);
    pack_w2_kernel<<<(H * 32 + 255) / 256, 256>>>(w2);
    dim3 gtr(H / 64, H / 64);
    pack_v1T_kernel<<<gtr, 256>>>(v1);

    dim3 gg(TPAD / 32, H / 256);          // 32 x 16 blocks, 256 threads
    gemm_in_imma<<<gg, 256>>>();

    snn_recur_kernel<<<1, 288>>>(d_out);
}

// round 11
// speedup vs baseline: 1.0008x; 1.0008x over previous
#include <cuda_runtime.h>
#include <stdint.h>
#include <math.h>

#define NI 700
#define NIP 704
#define H 4096
#define T 1000
#define TPAD 1024
#define O 20

// ---------------- scratch (static device memory; no allocs) ----------------
__device__ __align__(16) int8_t  g_w1p[H * NIP];        // w1 packed int8, padded 700->704
__device__ __align__(16) int8_t  g_sp [TPAD * NIP];     // spikes packed int8, padded rows+cols
__device__ __align__(16) uint8_t g_v1B[(size_t)H * H];  // v1B[k][h] = v1[h][k] + 8  (0..15)
__device__ __align__(16) int8_t  g_w2T[H * 32];         // w2T[k][o], padded 20->32
__device__ __align__(16) int     g_in [T * H];          // in_all[t][h], int32 (exact)
__device__ int g_mode;  // input dtype: 0=int64, 1=int32, 2=float32, 3=float64

// ---------------- input dtype probe (on w1: dense values in [-8,7]) ----------------
__global__ void detect_dtype_kernel(const void* __restrict__ p) {
    const int* w = (const int*)p;
    bool i64 = true;
    for (int i = 0; i < 8; i++) {
        int lo = w[2 * i], hi = w[2 * i + 1];
        if (!(lo >= -8 && lo <= 7 && hi == (lo < 0 ? -1 : 0))) i64 = false;
    }
    if (i64) { g_mode = 0; return; }
    bool i32 = true;
    for (int i = 0; i < 16; i++) {
        int v = w[i];
        if (!(v >= -8 && v <= 7)) i32 = false;
    }
    if (i32) { g_mode = 1; return; }
    bool f32 = true;
    for (int i = 0; i < 16; i++) {
        float f = __int_as_float(w[i]);
        if (!(isfinite(f) && fabsf(f) <= 8.0f && f == truncf(f))) f32 = false;
    }
    if (f32) { g_mode = 2; return; }
    g_mode = 3;  // float64
}

__device__ __forceinline__ int load_elem(const void* p, long idx) {
    switch (g_mode) {
        case 0:  return (int)((const long long*)p)[idx];
        case 1:  return ((const int*)p)[idx];
        case 2:  return (int)((const float*)p)[idx];
        default: return (int)((const double*)p)[idx];
    }
}

// ---------------- pack kernels ----------------
__global__ void pack_w1_kernel(const void* __restrict__ w1) {
    int idx = blockIdx.x * blockDim.x + threadIdx.x;
    if (idx >= H * NIP) return;
    int h = idx / NIP, c = idx - h * NIP;
    g_w1p[idx] = (c < NI) ? (int8_t)load_elem(w1, (long)h * NI + c) : (int8_t)0;
}

__global__ void pack_sp_kernel(const void* __restrict__ spk) {
    int idx = blockIdx.x * blockDim.x + threadIdx.x;
    if (idx >= TPAD * NIP) return;
    int t = idx / NIP, c = idx - t * NIP;
    g_sp[idx] = (t < T && c < NI) ? (int8_t)load_elem(spk, (long)t * NI + c) : (int8_t)0;
}

__global__ void pack_w2_kernel(const void* __restrict__ w2) {
    int idx = blockIdx.x * blockDim.x + threadIdx.x;
    if (idx >= H * 32) return;
    int k = idx >> 5, o = idx & 31;
    g_w2T[idx] = (o < O) ? (int8_t)load_elem(w2, (long)o * H + k) : (int8_t)0;
}

// tiled transpose: v1[h][k] -> g_v1B[k][h] = v1[h][k] + 8 (biased uint8)
__global__ void pack_v1T_kernel(const void* __restrict__ v1) {
    __shared__ uint8_t tile[64][65];
    int kb = blockIdx.x * 64;
    int hb = blockIdx.y * 64;
    for (int i = threadIdx.x; i < 64 * 64; i += 256) {
        int r = i >> 6, c = i & 63;          // r = h-local, c = k-local
        tile[c][r] = (uint8_t)(load_elem(v1, (long)(hb + r) * H + (kb + c)) + 8);
    }
    __syncthreads();
    for (int i = threadIdx.x; i < 64 * 64; i += 256) {
        int r = i >> 6, c = i & 63;          // r = k-local, c = h-local
        g_v1B[(size_t)(kb + r) * H + (hb + c)] = tile[r][c];
    }
}

// ---------------- feed-forward GEMM via IMMA tensor cores ----------------
__device__ __forceinline__ void mma16832(int* d, const unsigned* a, const unsigned* b) {
    asm volatile(
        "mma.sync.aligned.m16n8k32.row.col.s32.s8.s8.s32 "
        "{%0,%1,%2,%3},{%4,%5,%6,%7},{%8,%9},{%0,%1,%2,%3};"
        : "+r"(d[0]), "+r"(d[1]), "+r"(d[2]), "+r"(d[3])
        : "r"(a[0]), "r"(a[1]), "r"(a[2]), "r"(a[3]), "r"(b[0]), "r"(b[1]));
}

__global__ void __launch_bounds__(256, 1) gemm_in_imma() {
    const int warp = threadIdx.x >> 5;
    const int lane = threadIdx.x & 31;
    const int gid = lane >> 2;           // group id (0..7)
    const int tig = lane & 3;            // thread-in-group (0..3)
    const int tb = blockIdx.x * 32;      // t-tile base (rows, padded to 1024)
    const int hb = blockIdx.y * 256 + warp * 32;  // h-tile base

    int acc[2][4][4];
#pragma unroll
    for (int mt = 0; mt < 2; mt++)
#pragma unroll
        for (int nt = 0; nt < 4; nt++)
#pragma unroll
            for (int r = 0; r < 4; r++) acc[mt][nt][r] = 0;

    const int8_t* As = g_sp  + (size_t)(tb + gid) * NIP + tig * 4;
    const int8_t* Bs = g_w1p + (size_t)(hb + gid) * NIP + tig * 4;

    for (int kk = 0; kk < NIP; kk += 32) {
        unsigned a[2][4], b[4][2];
#pragma unroll
        for (int mt = 0; mt < 2; mt++) {
            const int8_t* ap = As + (size_t)mt * 16 * NIP + kk;
            a[mt][0] = *(const unsigned*)(ap);
            a[mt][1] = *(const unsigned*)(ap + 8 * NIP);
            a[mt][2] = *(const unsigned*)(ap + 16);
            a[mt][3] = *(const unsigned*)(ap + 8 * NIP + 16);
        }
#pragma unroll
        for (int nt = 0; nt < 4; nt++) {
            const int8_t* bp = Bs + (size_t)nt * 8 * NIP + kk;
            b[nt][0] = *(const unsigned*)(bp);
            b[nt][1] = *(const unsigned*)(bp + 16);
        }
#pragma unroll
        for (int mt = 0; mt < 2; mt++)
#pragma unroll
            for (int nt = 0; nt < 4; nt++)
                mma16832(acc[mt][nt], a[mt], b[nt]);
    }

#pragma unroll
    for (int mt = 0; mt < 2; mt++) {
#pragma unroll
        for (int nt = 0; nt < 4; nt++) {
            int row0 = tb + mt * 16 + gid;
            int col = hb + nt * 8 + tig * 2;
            if (row0 < T)
                *(int2*)(g_in + (size_t)row0 * H + col) =
                    make_int2(acc[mt][nt][0], acc[mt][nt][1]);
            int row1 = row0 + 8;
            if (row1 < T)
                *(int2*)(g_in + (size_t)row1 * H + col) =
                    make_int2(acc[mt][nt][2], acc[mt][nt][3]);
        }
    }
}

// LIF update for one neuron (constant index i at expansion site).
#define LIF1(i, icval) do {                                                    \
    int m = ((spm >> (i)) & 1u) ? 0 : mem[i];                                  \
    nm |= (unsigned)(m > 1) << (i);                                            \
    mem[i] = m - (m >> 3) + syn[i];                                            \
    syn[i] = syn[i] - (syn[i] >> 4) + (icval) + (int)accu[i] - bias;           \
} while (0)

// ---------------- sequential recurrence: one persistent CTA, 288 threads ----
// Threads 0..255: gather+LIF, 16 neurons each. Biased-byte accumulation with
// EXPLICIT 4-deep load batching (MLP) inside each <=16-row chunk. Warp 8:
// readout, also 4-deep batched. One barrier per step.
__global__ void __launch_bounds__(288, 1) snn_recur_kernel(void* __restrict__ out) {
    __shared__ int listbuf[2][H];
    __shared__ int cnts[T + 1];
    const int tid = threadIdx.x;
    const bool gth = tid < 256;
    const int h0 = tid << 4;             // first neuron (also row byte offset)
    const int ro_lane = tid - 256;

    int mem[16], syn[16];
    unsigned accu[16];
    unsigned spm = 0;                    // previous-step spike bitmask
    int rm = 0, rs = 0;                  // readout state
#pragma unroll
    for (int i = 0; i < 16; i++) { mem[i] = 0; syn[i] = 0; }

    for (int i = tid; i <= T; i += 288) cnts[i] = 0;
    __syncthreads();

    for (int t = 0; t < T; t++) {
        const int p = t & 1, pn = p ^ 1;
        const int n = cnts[t];           // spikes produced at step t-1
        const int* lb = listbuf[p];

        if (gth) {
            // prefetch this step's input currents (hidden behind the gather)
            const int4* gi = (const int4*)(g_in + (size_t)t * H + h0);
            int4 ic0 = __ldg(gi + 0), ic1 = __ldg(gi + 1);
            int4 ic2 = __ldg(gi + 2), ic3 = __ldg(gi + 3);

#pragma unroll
            for (int i = 0; i < 16; i++) accu[i] = 0;

            const uint8_t* vbase = g_v1B + h0;
            int j = 0;
            while (j < n) {
                int e = j + 16; if (e > n) e = n;     // chunk of <=16 rows
                unsigned pa = 0, pb = 0, pc = 0, pd = 0;
                // 4-deep batches: independent LDG.128s, then sum
                for (; j + 4 <= e; j += 4) {
                    uint4 A = *(const uint4*)(vbase + ((size_t)lb[j]     << 12));
                    uint4 B = *(const uint4*)(vbase + ((size_t)lb[j + 1] << 12));
                    uint4 C = *(const uint4*)(vbase + ((size_t)lb[j + 2] << 12));
                    uint4 D = *(const uint4*)(vbase + ((size_t)lb[j + 3] << 12));
                    pa += A.x + B.x + C.x + D.x;
                    pb += A.y + B.y + C.y + D.y;
                    pc += A.z + B.z + C.z + D.z;
                    pd += A.w + B.w + C.w + D.w;
                }
                for (; j < e; j++) {      // tail (0..3 rows)
                    uint4 R = *(const uint4*)(vbase + ((size_t)lb[j] << 12));
                    pa += R.x; pb += R.y; pc += R.z; pd += R.w;
                }
                accu[0]  = __dp4a(pa, 0x00000001u, accu[0]);
                accu[1]  = __dp4a(pa, 0x00000100u, accu[1]);
                accu[2]  = __dp4a(pa, 0x00010000u, accu[2]);
                accu[3]  = __dp4a(pa, 0x01000000u, accu[3]);
                accu[4]  = __dp4a(pb, 0x00000001u, accu[4]);
                accu[5]  = __dp4a(pb, 0x00000100u, accu[5]);
                accu[6]  = __dp4a(pb, 0x00010000u, accu[6]);
                accu[7]  = __dp4a(pb, 0x01000000u, accu[7]);
                accu[8]  = __dp4a(pc, 0x00000001u, accu[8]);
                accu[9]  = __dp4a(pc, 0x00000100u, accu[9]);
                accu[10] = __dp4a(pc, 0x00010000u, accu[10]);
                accu[11] = __dp4a(pc, 0x01000000u, accu[11]);
                accu[12] = __dp4a(pd, 0x00000001u, accu[12]);
                accu[13] = __dp4a(pd, 0x00000100u, accu[13]);
                accu[14] = __dp4a(pd, 0x00010000u, accu[14]);
                accu[15] = __dp4a(pd, 0x01000000u, accu[15]);
            }
            const int bias = n * 8;

            // ---- LIF (reset by prev spike -> threshold -> decay/integrate) ----
            unsigned nm = 0;
            LIF1(0,  ic0.x); LIF1(1,  ic0.y); LIF1(2,  ic0.z); LIF1(3,  ic0.w);
            LIF1(4,  ic1.x); LIF1(5,  ic1.y); LIF1(6,  ic1.z); LIF1(7,  ic1.w);
            LIF1(8,  ic2.x); LIF1(9,  ic2.y); LIF1(10, ic2.z); LIF1(11, ic2.w);
            LIF1(12, ic3.x); LIF1(13, ic3.y); LIF1(14, ic3.z); LIF1(15, ic3.w);

            // ---- append new spikes ----
            int c = __popc(nm);
            if (c) {
                int pos = atomicAdd(&cnts[t + 1], c);
                unsigned b = nm;
                while (b) {
                    int i = __ffs(b) - 1;
                    b &= b - 1;
                    listbuf[pn][pos++] = h0 + i;
                }
            }
            spm = nm;
        } else if (t > 0) {
            // ---- readout for step t-1 (warp 8, 4-deep batched loads) ----
            int ro = 0;
            int j = 0;
            for (; j + 4 <= n; j += 4) {
                int a = (int)g_w2T[(lb[j]     << 5) + ro_lane];
                int b = (int)g_w2T[(lb[j + 1] << 5) + ro_lane];
                int c = (int)g_w2T[(lb[j + 2] << 5) + ro_lane];
                int d = (int)g_w2T[(lb[j + 3] << 5) + ro_lane];
                ro += a + b + c + d;
            }
            for (; j < n; j++)
                ro += (int)g_w2T[(lb[j] << 5) + ro_lane];
            rm = rm - (rm >> 3) + rs;
            rs = rs - (rs >> 4) + ro;
            if (ro_lane < O) ((float*)out)[ro_lane * T + (t - 1)] = (float)rm;
        }

        __syncthreads();                 // publish listbuf[pn] + cnts[t+1]
    }

    // ---- epilogue: readout for t = T-1 (no gather needed) ----
    if (!gth) {
        rm = rm - (rm >> 3) + rs;
        if (ro_lane < O) ((float*)out)[ro_lane * T + (T - 1)] = (float)rm;
    }
}

// ---------------- launcher ----------------
extern "C" void kernel_launch(void* const* d_in, const int* in_sizes, int n_in,
                              void* d_out, int out_size) {
    // Identify inputs by element count (order-independent; all sizes unique).
    const void *spk = 0, *w1 = 0, *v1 = 0, *w2 = 0;
    for (int i = 0; i < n_in; i++) {
        switch (in_sizes[i]) {
            case T * NI:  spk = d_in[i]; break;   // 700,000
            case H * NI:  w1  = d_in[i]; break;   // 2,867,200
            case H * H:   v1  = d_in[i]; break;   // 16,777,216
            case O * H:   w2  = d_in[i]; break;   // 81,920
        }
    }

    detect_dtype_kernel<<<1, 1>>>(w1);

    pack_w1_kernel<<<(H * NIP + 255) / 256, 256>>>(w1);
    pack_sp_kernel<<<(TPAD * NIP + 255) / 256, 256>>>(spk);
    pack_w2_kernel<<<(H * 32 + 255) / 256, 256>>>(w2);
    dim3 gtr(H / 64, H / 64);
    pack_v1T_kernel<<<gtr, 256>>>(v1);

    dim3 gg(TPAD / 32, H / 256);          // 32 x 16 blocks, 256 threads
    gemm_in_imma<<<gg, 256>>>();

    snn_recur_kernel<<<1, 288>>>(d_out);
}

// round 12
// speedup vs baseline: 1.0010x; 1.0002x over previous
#include <cuda_runtime.h>
#include <stdint.h>
#include <math.h>

#define NI 700
#define NIP 704
#define H 4096
#define T 1000
#define TPAD 1024
#define O 20

// ---------------- scratch (static device memory; no allocs) ----------------
__device__ __align__(16) int8_t  g_w1p[H * NIP];        // w1 packed int8, padded 700->704
__device__ __align__(16) int8_t  g_sp [TPAD * NIP];     // spikes packed int8, padded rows+cols
__device__ __align__(16) uint8_t g_v1B[(size_t)H * H];  // v1B[k][h] = v1[h][k] + 8  (0..15)
__device__ __align__(16) int8_t  g_w2T[H * 32];         // w2T[k][o], padded 20->32
__device__ __align__(16) int     g_in [T * H];          // in_all[t][h], int32 (exact)
__device__ int g_mode;  // input dtype: 0=int64, 1=int32, 2=float32, 3=float64

// ---------------- input dtype probe (on w1: dense values in [-8,7]) ----------------
__global__ void detect_dtype_kernel(const void* __restrict__ p) {
    const int* w = (const int*)p;
    bool i64 = true;
    for (int i = 0; i < 8; i++) {
        int lo = w[2 * i], hi = w[2 * i + 1];
        if (!(lo >= -8 && lo <= 7 && hi == (lo < 0 ? -1 : 0))) i64 = false;
    }
    if (i64) { g_mode = 0; return; }
    bool i32 = true;
    for (int i = 0; i < 16; i++) {
        int v = w[i];
        if (!(v >= -8 && v <= 7)) i32 = false;
    }
    if (i32) { g_mode = 1; return; }
    bool f32 = true;
    for (int i = 0; i < 16; i++) {
        float f = __int_as_float(w[i]);
        if (!(isfinite(f) && fabsf(f) <= 8.0f && f == truncf(f))) f32 = false;
    }
    if (f32) { g_mode = 2; return; }
    g_mode = 3;  // float64
}

__device__ __forceinline__ int load_elem(const void* p, long idx) {
    switch (g_mode) {
        case 0:  return (int)((const long long*)p)[idx];
        case 1:  return ((const int*)p)[idx];
        case 2:  return (int)((const float*)p)[idx];
        default: return (int)((const double*)p)[idx];
    }
}

// ---------------- pack kernels ----------------
__global__ void pack_w1_kernel(const void* __restrict__ w1) {
    int idx = blockIdx.x * blockDim.x + threadIdx.x;
    if (idx >= H * NIP) return;
    int h = idx / NIP, c = idx - h * NIP;
    g_w1p[idx] = (c < NI) ? (int8_t)load_elem(w1, (long)h * NI + c) : (int8_t)0;
}

__global__ void pack_sp_kernel(const void* __restrict__ spk) {
    int idx = blockIdx.x * blockDim.x + threadIdx.x;
    if (idx >= TPAD * NIP) return;
    int t = idx / NIP, c = idx - t * NIP;
    g_sp[idx] = (t < T && c < NI) ? (int8_t)load_elem(spk, (long)t * NI + c) : (int8_t)0;
}

__global__ void pack_w2_kernel(const void* __restrict__ w2) {
    int idx = blockIdx.x * blockDim.x + threadIdx.x;
    if (idx >= H * 32) return;
    int k = idx >> 5, o = idx & 31;
    g_w2T[idx] = (o < O) ? (int8_t)load_elem(w2, (long)o * H + k) : (int8_t)0;
}

// tiled transpose: v1[h][k] -> g_v1B[k][h] = v1[h][k] + 8 (biased uint8)
__global__ void pack_v1T_kernel(const void* __restrict__ v1) {
    __shared__ uint8_t tile[64][65];
    int kb = blockIdx.x * 64;
    int hb = blockIdx.y * 64;
    for (int i = threadIdx.x; i < 64 * 64; i += 256) {
        int r = i >> 6, c = i & 63;          // r = h-local, c = k-local
        tile[c][r] = (uint8_t)(load_elem(v1, (long)(hb + r) * H + (kb + c)) + 8);
    }
    __syncthreads();
    for (int i = threadIdx.x; i < 64 * 64; i += 256) {
        int r = i >> 6, c = i & 63;          // r = k-local, c = h-local
        g_v1B[(size_t)(kb + r) * H + (hb + c)] = tile[r][c];
    }
}

// ---------------- feed-forward GEMM via IMMA tensor cores ----------------
__device__ __forceinline__ void mma16832(int* d, const unsigned* a, const unsigned* b) {
    asm volatile(
        "mma.sync.aligned.m16n8k32.row.col.s32.s8.s8.s32 "
        "{%0,%1,%2,%3},{%4,%5,%6,%7},{%8,%9},{%0,%1,%2,%3};"
        : "+r"(d[0]), "+r"(d[1]), "+r"(d[2]), "+r"(d[3])
        : "r"(a[0]), "r"(a[1]), "r"(a[2]), "r"(a[3]), "r"(b[0]), "r"(b[1]));
}

__global__ void __launch_bounds__(256, 1) gemm_in_imma() {
    const int warp = threadIdx.x >> 5;
    const int lane = threadIdx.x & 31;
    const int gid = lane >> 2;           // group id (0..7)
    const int tig = lane & 3;            // thread-in-group (0..3)
    const int tb = blockIdx.x * 32;      // t-tile base (rows, padded to 1024)
    const int hb = blockIdx.y * 256 + warp * 32;  // h-tile base

    int acc[2][4][4];
#pragma unroll
    for (int mt = 0; mt < 2; mt++)
#pragma unroll
        for (int nt = 0; nt < 4; nt++)
#pragma unroll
            for (int r = 0; r < 4; r++) acc[mt][nt][r] = 0;

    const int8_t* As = g_sp  + (size_t)(tb + gid) * NIP + tig * 4;
    const int8_t* Bs = g_w1p + (size_t)(hb + gid) * NIP + tig * 4;

    for (int kk = 0; kk < NIP; kk += 32) {
        unsigned a[2][4], b[4][2];
#pragma unroll
        for (int mt = 0; mt < 2; mt++) {
            const int8_t* ap = As + (size_t)mt * 16 * NIP + kk;
            a[mt][0] = *(const unsigned*)(ap);
            a[mt][1] = *(const unsigned*)(ap + 8 * NIP);
            a[mt][2] = *(const unsigned*)(ap + 16);
            a[mt][3] = *(const unsigned*)(ap + 8 * NIP + 16);
        }
#pragma unroll
        for (int nt = 0; nt < 4; nt++) {
            const int8_t* bp = Bs + (size_t)nt * 8 * NIP + kk;
            b[nt][0] = *(const unsigned*)(bp);
            b[nt][1] = *(const unsigned*)(bp + 16);
        }
#pragma unroll
        for (int mt = 0; mt < 2; mt++)
#pragma unroll
            for (int nt = 0; nt < 4; nt++)
                mma16832(acc[mt][nt], a[mt], b[nt]);
    }

#pragma unroll
    for (int mt = 0; mt < 2; mt++) {
#pragma unroll
        for (int nt = 0; nt < 4; nt++) {
            int row0 = tb + mt * 16 + gid;
            int col = hb + nt * 8 + tig * 2;
            if (row0 < T)
                *(int2*)(g_in + (size_t)row0 * H + col) =
                    make_int2(acc[mt][nt][0], acc[mt][nt][1]);
            int row1 = row0 + 8;
            if (row1 < T)
                *(int2*)(g_in + (size_t)row1 * H + col) =
                    make_int2(acc[mt][nt][2], acc[mt][nt][3]);
        }
    }
}

// LIF update for one neuron (constant index i at expansion site).
#define LIF1(i, icval) do {                                                    \
    int m = ((spm >> (i)) & 1u) ? 0 : mem[i];                                  \
    nm |= (unsigned)(m > 1) << (i);                                            \
    mem[i] = m - (m >> 3) + syn[i];                                            \
    syn[i] = syn[i] - (syn[i] >> 4) + (icval) + (int)accu[i] - bias;           \
} while (0)

// ---------------- sequential recurrence: one persistent CTA, 288 threads ----
// Threads 0..255: gather+LIF, 16 neurons each. Biased-byte accumulation with
// EXPLICIT 4-deep load batching (MLP) inside each <=16-row chunk. Warp 8:
// readout, also 4-deep batched. One barrier per step.
__global__ void __launch_bounds__(288, 1) snn_recur_kernel(void* __restrict__ out) {
    __shared__ int listbuf[2][H];
    __shared__ int cnts[T + 1];
    const int tid = threadIdx.x;
    const bool gth = tid < 256;
    const int h0 = tid << 4;             // first neuron (also row byte offset)
    const int ro_lane = tid - 256;

    int mem[16], syn[16];
    unsigned accu[16];
    unsigned spm = 0;                    // previous-step spike bitmask
    int rm = 0, rs = 0;                  // readout state
#pragma unroll
    for (int i = 0; i < 16; i++) { mem[i] = 0; syn[i] = 0; }

    for (int i = tid; i <= T; i += 288) cnts[i] = 0;
    __syncthreads();

    for (int t = 0; t < T; t++) {
        const int p = t & 1, pn = p ^ 1;
        const int n = cnts[t];           // spikes produced at step t-1
        const int* lb = listbuf[p];

        if (gth) {
            // prefetch this step's input currents (hidden behind the gather)
            const int4* gi = (const int4*)(g_in + (size_t)t * H + h0);
            int4 ic0 = __ldg(gi + 0), ic1 = __ldg(gi + 1);
            int4 ic2 = __ldg(gi + 2), ic3 = __ldg(gi + 3);

#pragma unroll
            for (int i = 0; i < 16; i++) accu[i] = 0;

            const uint8_t* vbase = g_v1B + h0;
            int j = 0;
            while (j < n) {
                int e = j + 16; if (e > n) e = n;     // chunk of <=16 rows
                unsigned pa = 0, pb = 0, pc = 0, pd = 0;
                // 4-deep batches: independent LDG.128s, then sum
                for (; j + 4 <= e; j += 4) {
                    uint4 A = *(const uint4*)(vbase + ((size_t)lb[j]     << 12));
                    uint4 B = *(const uint4*)(vbase + ((size_t)lb[j + 1] << 12));
                    uint4 C = *(const uint4*)(vbase + ((size_t)lb[j + 2] << 12));
                    uint4 D = *(const uint4*)(vbase + ((size_t)lb[j + 3] << 12));
                    pa += A.x + B.x + C.x + D.x;
                    pb += A.y + B.y + C.y + D.y;
                    pc += A.z + B.z + C.z + D.z;
                    pd += A.w + B.w + C.w + D.w;
                }
                for (; j < e; j++) {      // tail (0..3 rows)
                    uint4 R = *(const uint4*)(vbase + ((size_t)lb[j] << 12));
                    pa += R.x; pb += R.y; pc += R.z; pd += R.w;
                }
                accu[0]  = __dp4a(pa, 0x00000001u, accu[0]);
                accu[1]  = __dp4a(pa, 0x00000100u, accu[1]);
                accu[2]  = __dp4a(pa, 0x00010000u, accu[2]);
                accu[3]  = __dp4a(pa, 0x01000000u, accu[3]);
                accu[4]  = __dp4a(pb, 0x00000001u, accu[4]);
                accu[5]  = __dp4a(pb, 0x00000100u, accu[5]);
                accu[6]  = __dp4a(pb, 0x00010000u, accu[6]);
                accu[7]  = __dp4a(pb, 0x01000000u, accu[7]);
                accu[8]  = __dp4a(pc, 0x00000001u, accu[8]);
                accu[9]  = __dp4a(pc, 0x00000100u, accu[9]);
                accu[10] = __dp4a(pc, 0x00010000u, accu[10]);
                accu[11] = __dp4a(pc, 0x01000000u, accu[11]);
                accu[12] = __dp4a(pd, 0x00000001u, accu[12]);
                accu[13] = __dp4a(pd, 0x00000100u, accu[13]);
                accu[14] = __dp4a(pd, 0x00010000u, accu[14]);
                accu[15] = __dp4a(pd, 0x01000000u, accu[15]);
            }
            const int bias = n * 8;

            // ---- LIF (reset by prev spike -> threshold -> decay/integrate) ----
            unsigned nm = 0;
            LIF1(0,  ic0.x); LIF1(1,  ic0.y); LIF1(2,  ic0.z); LIF1(3,  ic0.w);
            LIF1(4,  ic1.x); LIF1(5,  ic1.y); LIF1(6,  ic1.z); LIF1(7,  ic1.w);
            LIF1(8,  ic2.x); LIF1(9,  ic2.y); LIF1(10, ic2.z); LIF1(11, ic2.w);
            LIF1(12, ic3.x); LIF1(13, ic3.y); LIF1(14, ic3.z); LIF1(15, ic3.w);

            // ---- append new spikes ----
            int c = __popc(nm);
            if (c) {
                int pos = atomicAdd(&cnts[t + 1], c);
                unsigned b = nm;
                while (b) {
                    int i = __ffs(b) - 1;
                    b &= b - 1;
                    listbuf[pn][pos++] = h0 + i;
                }
            }
            spm = nm;
        } else if (t > 0) {
            // ---- readout for step t-1 (warp 8, 4-deep batched loads) ----
            int ro = 0;
            int j = 0;
            for (; j + 4 <= n; j += 4) {
                int a = (int)g_w2T[(lb[j]     << 5) + ro_lane];
                int b = (int)g_w2T[(lb[j + 1] << 5) + ro_lane];
                int c = (int)g_w2T[(lb[j + 2] << 5) + ro_lane];
                int d = (int)g_w2T[(lb[j + 3] << 5) + ro_lane];
                ro += a + b + c + d;
            }
            for (; j < n; j++)
                ro += (int)g_w2T[(lb[j] << 5) + ro_lane];
            rm = rm - (rm >> 3) + rs;
            rs = rs - (rs >> 4) + ro;
            if (ro_lane < O) ((float*)out)[ro_lane * T + (t - 1)] = (float)rm;
        }

        __syncthreads();                 // publish listbuf[pn] + cnts[t+1]
    }

    // ---- epilogue: readout for t = T-1 (no gather needed) ----
    if (!gth) {
        rm = rm - (rm >> 3) + rs;
        if (ro_lane < O) ((float*)out)[ro_lane * T + (T - 1)] = (float)rm;
    }
}

// ---------------- launcher ----------------
extern "C" void kernel_launch(void* const* d_in, const int* in_sizes, int n_in,
                              void* d_out, int out_size) {
    // Identify inputs by element count (order-independent; all sizes unique).
    const void *spk = 0, *w1 = 0, *v1 = 0, *w2 = 0;
    for (int i = 0; i < n_in; i++) {
        switch (in_sizes[i]) {
            case T * NI:  spk = d_in[i]; break;   // 700,000
            case H * NI:  w1  = d_in[i]; break;   // 2,867,200
            case H * H:   v1  = d_in[i]; break;   // 16,777,216
            case O * H:   w2  = d_in[i]; break;   // 81,920
        }
    }

    detect_dtype_kernel<<<1, 1>>>(w1);

    pack_w1_kernel<<<(H * NIP + 255) / 256, 256>>>(w1);
    pack_sp_kernel<<<(TPAD * NIP + 255) / 256, 256>>>(spk);
    pack_w2_kernel<<<(H * 32 + 255) / 256, 256>>>(w2);
    dim3 gtr(H / 64, H / 64);
    pack_v1T_kernel<<<gtr, 256>>>(v1);

    dim3 gg(TPAD / 32, H / 256);          // 32 x 16 blocks, 256 threads
    gemm_in_imma<<<gg, 256>>>();

    snn_recur_kernel<<<1, 288>>>(d_out);
}